// round 9
// baseline (speedup 1.0000x reference)
#include <cuda_runtime.h>
#include <cuda_bf16.h>
#include <math_constants.h>

// ProbAttention (Informer ProbSparse) — B=4, L=S=2048, H=8, D=64, sample_k=n_top=40.
// Inputs (metadata order): queries f32 [B,L,H,D], keys f32 [B,S,H,D],
//                          values f32 [B,S,H,D], index_sample i32 [L,40].
// Output f32 [B,L,H,D].

#define B_ 4
#define L_ 2048
#define S_ 2048
#define H_ 8
#define D_ 64
#define SK_ 40
#define NTOP_ 40
#define BH_ (B_ * H_)
#define SCALE_ 0.125f
#define QPB_ 4
#define QBLKS_ (NTOP_ / QPB_)

#define CHUNK_ 256                   // l-chunk per sample block
#define NCHUNK_ (L_ / CHUNK_)        // 8
#define NBUCK_ (NCHUNK_ * S_)        // 16384 buckets (chunk, s)
#define NPAIR_ (L_ * SK_)            // 81920 sampled (l,s) pairs
#define TILE_S_ 128                  // k-rows staged per smem tile

// Scratch (__device__ globals: allocation-free rule)
__device__ int   g_cnt[NBUCK_ + 1];
__device__ int   g_off[NBUCK_ + 1];
__device__ int   g_pos[NBUCK_];
__device__ int   g_pairs[NPAIR_];    // packed (s<<11)|l
__device__ float g_M[BH_ * L_];
__device__ int   g_top[BH_ * NTOP_];
__device__ float g_vmean[BH_ * D_];

// Order-preserving float<->uint transform (for atomicMax on floats)
__device__ __forceinline__ unsigned ford(float f) {
    unsigned u = __float_as_uint(f);
    return (u & 0x80000000u) ? ~u : (u | 0x80000000u);
}
__device__ __forceinline__ float funord(unsigned u) {
    u = (u & 0x80000000u) ? (u & 0x7FFFFFFFu) : ~u;
    return __uint_as_float(u);
}

// ---------------------------------------------------------------------------
// Inverse-index build: zero -> histogram -> scan -> scatter
// ---------------------------------------------------------------------------
__global__ void k_zero() {
    int i = blockIdx.x * blockDim.x + threadIdx.x;
    if (i < NBUCK_) { g_cnt[i] = 0; g_pos[i] = 0; }
}

__global__ void k_hist(const int* __restrict__ idxs) {
    int i = blockIdx.x * blockDim.x + threadIdx.x;
    if (i >= NPAIR_) return;
    int l = i / SK_;
    int s = idxs[i];
    atomicAdd(&g_cnt[(l >> 8) * S_ + s], 1);
}

__global__ __launch_bounds__(1024) void k_scan() {
    // exclusive prefix over 16384 counts; 1 block, 16 per thread
    __shared__ int sums[1024];
    int tid = threadIdx.x;
    int base = tid * 16;
    int loc[16];
    int run = 0;
    #pragma unroll
    for (int j = 0; j < 16; j++) { loc[j] = run; run += g_cnt[base + j]; }
    sums[tid] = run;
    __syncthreads();
    for (int off = 1; off < 1024; off <<= 1) {
        int v = (tid >= off) ? sums[tid - off] : 0;
        __syncthreads();
        sums[tid] += v;
        __syncthreads();
    }
    int myoff = tid ? sums[tid - 1] : 0;
    #pragma unroll
    for (int j = 0; j < 16; j++) g_off[base + j] = myoff + loc[j];
    if (tid == 1023) g_off[NBUCK_] = sums[1023];
}

__global__ void k_scatter(const int* __restrict__ idxs) {
    int i = blockIdx.x * blockDim.x + threadIdx.x;
    if (i >= NPAIR_) return;
    int l = i / SK_;
    int s = idxs[i];
    int bucket = (l >> 8) * S_ + s;
    int pos = g_off[bucket] + atomicAdd(&g_pos[bucket], 1);
    g_pairs[pos] = (s << 11) | l;
}

// ---------------------------------------------------------------------------
// K1 (s-major): block = (b,h,chunk). Q-chunk resident in smem; K streamed in
// tiles; pair list drives LDS+FMA dots; per-l max/sum via smem atomics.
// Dyn smem: q 64KB + ktile 32KB + accum 2KB = 100352 B.
// ---------------------------------------------------------------------------
#define SMEM_SAMPLE_ (CHUNK_ * D_ * 4 + TILE_S_ * D_ * 4 + CHUNK_ * 8)

__global__ __launch_bounds__(256) void k_sample(const float* __restrict__ q,
                                                const float* __restrict__ k) {
    extern __shared__ float dyn[];
    float*    q_s   = dyn;                                   // [CHUNK_][64] swizzled
    float*    k_t   = dyn + CHUNK_ * D_;                     // [TILE_S_][64] swizzled
    unsigned* m_max = (unsigned*)(k_t + TILE_S_ * D_);       // [CHUNK_]
    float*    m_sum = (float*)(m_max + CHUNK_);              // [CHUNK_]

    const int bhc = blockIdx.x;                // b*64 + h*8 + c
    const int c = bhc & 7, h = (bhc >> 3) & 7, b = bhc >> 6;
    const int t = threadIdx.x;

    if (t < CHUNK_) { m_max[t] = ford(-CUDART_INF_F); m_sum[t] = 0.f; }

    // Load q-chunk (256 rows x 256B), XOR-swizzled in float4 units
    {
        const float4* qg = (const float4*)q;
        for (int i = t; i < CHUNK_ * 16; i += 256) {
            int l = i >> 4, j = i & 15;
            float4 v = qg[(size_t)((b * L_ + (c * CHUNK_ + l)) * H_ + h) * 16 + j];
            ((float4*)q_s)[l * 16 + (j ^ (l & 7))] = v;
        }
    }

    const float4* kg = (const float4*)k;
    for (int s0 = 0; s0 < S_; s0 += TILE_S_) {
        __syncthreads();   // protect k_t from previous tile's readers
        for (int i = t; i < TILE_S_ * 16; i += 256) {
            int sr = i >> 4, j = i & 15;
            float4 v = kg[(size_t)((b * S_ + (s0 + sr)) * H_ + h) * 16 + j];
            ((float4*)k_t)[sr * 16 + (j ^ (sr & 7))] = v;
        }
        __syncthreads();

        int base = g_off[c * S_ + s0];
        int end  = g_off[c * S_ + s0 + TILE_S_];
        for (int e = base + t; e < end; e += 256) {
            int pk = g_pairs[e];
            int lr = pk & (CHUNK_ - 1);          // local l (chunk-owned)
            int sr = (pk >> 11) & (TILE_S_ - 1); // local s within tile
            const float4* qr = (const float4*)q_s + lr * 16;
            const float4* kr = (const float4*)k_t + sr * 16;
            float acc = 0.f;
            #pragma unroll
            for (int j = 0; j < 16; j++) {
                float4 a  = qr[j ^ (lr & 7)];
                float4 bb = kr[j ^ (sr & 7)];
                acc += a.x * bb.x + a.y * bb.y + a.z * bb.z + a.w * bb.w;
            }
            atomicMax(&m_max[lr], ford(acc));
            atomicAdd(&m_sum[lr], acc);
        }
    }
    __syncthreads();

    if (t < CHUNK_) {
        float mx = funord(m_max[t]);
        g_M[(size_t)(b * H_ + h) * L_ + c * CHUNK_ + t] =
            mx - m_sum[t] * (1.0f / (float)S_);
    }
}

// ---------------------------------------------------------------------------
// K2: top-40 per (b,h), register-resident iterative argmax on packed
// (ordered_value, ~index) 64-bit keys. Tie -> smaller index (matches top_k).
// ---------------------------------------------------------------------------
__global__ __launch_bounds__(1024) void k_topk() {
    int bh = blockIdx.x, t = threadIdx.x;
    int lane = t & 31, w = t >> 5;
    float v0 = g_M[(size_t)bh * L_ + 2 * t];
    float v1 = g_M[(size_t)bh * L_ + 2 * t + 1];

    __shared__ unsigned long long wbest[32];
    __shared__ unsigned long long winner;

    for (int it = 0; it < NTOP_; it++) {
        unsigned long long k0 =
            ((unsigned long long)ford(v0) << 32) | (unsigned)(~(2 * t));
        unsigned long long k1 =
            ((unsigned long long)ford(v1) << 32) | (unsigned)(~(2 * t + 1));
        unsigned long long kb = k0 > k1 ? k0 : k1;
        #pragma unroll
        for (int o = 16; o; o >>= 1) {
            unsigned long long ot = __shfl_xor_sync(0xFFFFFFFFu, kb, o);
            if (ot > kb) kb = ot;
        }
        if (lane == 0) wbest[w] = kb;
        __syncthreads();
        if (w == 0) {
            unsigned long long kk = wbest[lane];
            #pragma unroll
            for (int o = 16; o; o >>= 1) {
                unsigned long long ot = __shfl_xor_sync(0xFFFFFFFFu, kk, o);
                if (ot > kk) kk = ot;
            }
            if (lane == 0) winner = kk;
        }
        __syncthreads();
        unsigned widx = ~(unsigned)(winner & 0xFFFFFFFFu);
        if (t == 0) g_top[bh * NTOP_ + it] = (int)widx;
        if (widx == (unsigned)(2 * t))     v0 = -CUDART_INF_F;
        if (widx == (unsigned)(2 * t + 1)) v1 = -CUDART_INF_F;
    }
}

// ---------------------------------------------------------------------------
// K3: vmean[bh, d] = mean_s v[b,s,h,d]
// ---------------------------------------------------------------------------
__global__ void k_vmean(const float* __restrict__ v) {
    int bh = blockIdx.x;
    int b = bh >> 3, h = bh & 7;
    int tid = threadIdx.x;
    int d = tid & 63, g = tid >> 6;
    float s = 0.f;
    for (int r = g; r < S_; r += 4)
        s += v[(((size_t)(b * S_ + r)) * H_ + h) * D_ + d];
    __shared__ float part[4][D_];
    part[g][d] = s;
    __syncthreads();
    if (g == 0)
        g_vmean[bh * D_ + d] =
            (part[0][d] + part[1][d] + part[2][d] + part[3][d]) * (1.0f / (float)S_);
}

// ---------------------------------------------------------------------------
// K4: out[b,l,h,d] = vmean[bh,d]
// ---------------------------------------------------------------------------
__global__ void k_fill(float4* __restrict__ out) {
    unsigned i = blockIdx.x * blockDim.x + threadIdx.x;
    if (i >= (unsigned)(B_ * L_ * H_ * (D_ / 4))) return;
    unsigned d4 = i & 15u;
    unsigned h  = (i >> 4) & 7u;
    unsigned b  = i >> 18;
    const float4* vm = (const float4*)g_vmean;
    out[i] = __ldg(vm + ((b * H_ + h) * (D_ / 4) + d4));
}

// ---------------------------------------------------------------------------
// K5: dense attention for selected queries. 4 queries/block, scores in smem.
// ---------------------------------------------------------------------------
__global__ __launch_bounds__(256) void k_attn(const float* __restrict__ q,
                                              const float* __restrict__ k,
                                              const float* __restrict__ v,
                                              float* __restrict__ out) {
    int bh = blockIdx.x / QBLKS_;
    int qb = blockIdx.x % QBLKS_;
    int b = bh >> 3, h = bh & 7;
    int tid = threadIdx.x;

    __shared__ float sq[QPB_][D_];
    __shared__ float sc[QPB_][S_];
    __shared__ float sZ[QPB_];
    __shared__ int   sl[QPB_];
    __shared__ float pr[4][QPB_][D_];

    if (tid < QPB_ * D_) {
        int qi = tid >> 6, d = tid & 63;
        int lsel = g_top[bh * NTOP_ + qb * QPB_ + qi];
        if (d == 0) sl[qi] = lsel;
        sq[qi][d] = q[(((size_t)(b * L_ + lsel)) * H_ + h) * D_ + d] * SCALE_;
    }
    __syncthreads();

    for (int s = tid; s < S_; s += 256) {
        const float4* krow = (const float4*)(k + (((size_t)(b * S_ + s)) * H_ + h) * D_);
        float4 kr[16];
        #pragma unroll
        for (int j = 0; j < 16; j++) kr[j] = krow[j];
        #pragma unroll
        for (int qi = 0; qi < QPB_; qi++) {
            const float4* qq4 = (const float4*)sq[qi];
            float acc = 0.f;
            #pragma unroll
            for (int j = 0; j < 16; j++) {
                float4 qq = qq4[j];
                acc += qq.x * kr[j].x + qq.y * kr[j].y + qq.z * kr[j].z + qq.w * kr[j].w;
            }
            sc[qi][s] = acc;
        }
    }
    __syncthreads();

    int w = tid >> 5, lane = tid & 31;
    if (w < QPB_) {
        float mx = -CUDART_INF_F;
        for (int s = lane; s < S_; s += 32) mx = fmaxf(mx, sc[w][s]);
        #pragma unroll
        for (int o = 16; o; o >>= 1) mx = fmaxf(mx, __shfl_xor_sync(0xFFFFFFFFu, mx, o));
        float sum = 0.f;
        for (int s = lane; s < S_; s += 32) {
            float e = __expf(sc[w][s] - mx);
            sc[w][s] = e;
            sum += e;
        }
        #pragma unroll
        for (int o = 16; o; o >>= 1) sum += __shfl_xor_sync(0xFFFFFFFFu, sum, o);
        if (lane == 0) sZ[w] = sum;
    }
    __syncthreads();

    int d = tid & 63, g = tid >> 6;
    float acc[QPB_] = {0.f, 0.f, 0.f, 0.f};
    for (int s = g; s < S_; s += 4) {
        float vv = v[(((size_t)(b * S_ + s)) * H_ + h) * D_ + d];
        #pragma unroll
        for (int qi = 0; qi < QPB_; qi++) acc[qi] += sc[qi][s] * vv;
    }
    #pragma unroll
    for (int qi = 0; qi < QPB_; qi++) pr[g][qi][d] = acc[qi];
    __syncthreads();
    if (g < QPB_) {
        int qi = g;
        float r = (pr[0][qi][d] + pr[1][qi][d] + pr[2][qi][d] + pr[3][qi][d]) / sZ[qi];
        out[(((size_t)(b * L_ + sl[qi])) * H_ + h) * D_ + d] = r;
    }
}

// ---------------------------------------------------------------------------
extern "C" void kernel_launch(void* const* d_in, const int* in_sizes, int n_in,
                              void* d_out, int out_size) {
    const float* q   = (const float*)d_in[0];
    const float* k   = (const float*)d_in[1];
    const float* v   = (const float*)d_in[2];
    const int*   idx = (const int*)d_in[3];
    float* out = (float*)d_out;

    cudaFuncSetAttribute(k_sample, cudaFuncAttributeMaxDynamicSharedMemorySize,
                         SMEM_SAMPLE_);

    // Inverse index (same for all b,h)
    k_zero<<<(NBUCK_ + 255) / 256, 256>>>();
    k_hist<<<(NPAIR_ + 255) / 256, 256>>>(idx);
    k_scan<<<1, 1024>>>();
    k_scatter<<<(NPAIR_ + 255) / 256, 256>>>(idx);

    // Independent of sample path: mean(V) + broadcast fill
    k_vmean<<<BH_, 256>>>(v);
    {
        unsigned n4 = B_ * L_ * H_ * (D_ / 4);
        k_fill<<<(n4 + 255) / 256, 256>>>((float4*)out);
    }

    // s-major sampled QK -> M
    k_sample<<<B_ * H_ * NCHUNK_, 256, SMEM_SAMPLE_>>>(q, k);
    // top-40 per (b,h)
    k_topk<<<BH_, 1024>>>();
    // dense attention for selected rows (overwrites filled rows)
    k_attn<<<BH_ * QBLKS_, 256>>>(q, k, v, out);
}

// round 10
// speedup vs baseline: 1.1390x; 1.1390x over previous
#include <cuda_runtime.h>
#include <cuda_bf16.h>
#include <math_constants.h>

// ProbAttention (Informer ProbSparse) — B=4, L=S=2048, H=8, D=64, sample_k=n_top=40.
// Inputs (metadata order): queries f32 [B,L,H,D], keys f32 [B,S,H,D],
//                          values f32 [B,S,H,D], index_sample i32 [L,40].
// Output f32 [B,L,H,D].

#define B_ 4
#define L_ 2048
#define S_ 2048
#define H_ 8
#define D_ 64
#define SK_ 40
#define NTOP_ 40
#define BH_ (B_ * H_)
#define SCALE_ 0.125f
#define QPB_ 4
#define QBLKS_ (NTOP_ / QPB_)

#define CHUNK_ 256                   // l-chunk per sample block
#define NCHUNK_ (L_ / CHUNK_)        // 8
#define NBUCK_ (NCHUNK_ * S_)        // 16384 buckets (chunk, s)
#define NPAIR_ (L_ * SK_)            // 81920 sampled (l,s) pairs
#define TILE_S_ 128                  // k-rows staged per smem tile (k_sample)
#define ATILE_ 256                   // k-rows staged per smem tile (k_attn)

// Scratch (__device__ globals: allocation-free rule)
__device__ int   g_cnt[NBUCK_ + 1];
__device__ int   g_off[NBUCK_ + 1];
__device__ int   g_pos[NBUCK_];
__device__ int   g_pairs[NPAIR_];    // packed (s<<11)|l
__device__ float g_M[BH_ * L_];
__device__ int   g_top[BH_ * NTOP_];
__device__ float g_vmean[BH_ * D_];

// Order-preserving float<->uint transform (for atomicMax on floats)
__device__ __forceinline__ unsigned ford(float f) {
    unsigned u = __float_as_uint(f);
    return (u & 0x80000000u) ? ~u : (u | 0x80000000u);
}
__device__ __forceinline__ float funord(unsigned u) {
    u = (u & 0x80000000u) ? (u & 0x7FFFFFFFu) : ~u;
    return __uint_as_float(u);
}

// ---------------------------------------------------------------------------
// Inverse-index build: zero -> histogram -> scan -> scatter
// ---------------------------------------------------------------------------
__global__ void k_zero() {
    int i = blockIdx.x * blockDim.x + threadIdx.x;
    if (i < NBUCK_) { g_cnt[i] = 0; g_pos[i] = 0; }
    if (i < BH_ * D_) g_vmean[i] = 0.f;
}

__global__ void k_hist(const int* __restrict__ idxs) {
    int i = blockIdx.x * blockDim.x + threadIdx.x;
    if (i >= NPAIR_) return;
    int l = i / SK_;
    int s = idxs[i];
    atomicAdd(&g_cnt[(l >> 8) * S_ + s], 1);
}

__global__ __launch_bounds__(1024) void k_scan() {
    __shared__ int sums[1024];
    int tid = threadIdx.x;
    int base = tid * 16;
    int loc[16];
    int run = 0;
    #pragma unroll
    for (int j = 0; j < 16; j++) { loc[j] = run; run += g_cnt[base + j]; }
    sums[tid] = run;
    __syncthreads();
    for (int off = 1; off < 1024; off <<= 1) {
        int v = (tid >= off) ? sums[tid - off] : 0;
        __syncthreads();
        sums[tid] += v;
        __syncthreads();
    }
    int myoff = tid ? sums[tid - 1] : 0;
    #pragma unroll
    for (int j = 0; j < 16; j++) g_off[base + j] = myoff + loc[j];
    if (tid == 1023) g_off[NBUCK_] = sums[1023];
}

__global__ void k_scatter(const int* __restrict__ idxs) {
    int i = blockIdx.x * blockDim.x + threadIdx.x;
    if (i >= NPAIR_) return;
    int l = i / SK_;
    int s = idxs[i];
    int bucket = (l >> 8) * S_ + s;
    int pos = g_off[bucket] + atomicAdd(&g_pos[bucket], 1);
    g_pairs[pos] = (s << 11) | l;
}

// ---------------------------------------------------------------------------
// K1 (s-major): block = (b,h,chunk). Q-chunk in smem; K streamed in tiles;
// pair list drives LDS+FMA dots; per-l max/sum via smem atomics.
// ---------------------------------------------------------------------------
#define SMEM_SAMPLE_ (CHUNK_ * D_ * 4 + TILE_S_ * D_ * 4 + CHUNK_ * 8)

__global__ __launch_bounds__(256) void k_sample(const float* __restrict__ q,
                                                const float* __restrict__ k) {
    extern __shared__ float dyn[];
    float*    q_s   = dyn;                                   // [CHUNK_][64] swizzled
    float*    k_t   = dyn + CHUNK_ * D_;                     // [TILE_S_][64] swizzled
    unsigned* m_max = (unsigned*)(k_t + TILE_S_ * D_);       // [CHUNK_]
    float*    m_sum = (float*)(m_max + CHUNK_);              // [CHUNK_]

    const int bhc = blockIdx.x;
    const int c = bhc & 7, h = (bhc >> 3) & 7, b = bhc >> 6;
    const int t = threadIdx.x;

    if (t < CHUNK_) { m_max[t] = ford(-CUDART_INF_F); m_sum[t] = 0.f; }

    {
        const float4* qg = (const float4*)q;
        for (int i = t; i < CHUNK_ * 16; i += 256) {
            int l = i >> 4, j = i & 15;
            float4 v = qg[(size_t)((b * L_ + (c * CHUNK_ + l)) * H_ + h) * 16 + j];
            ((float4*)q_s)[l * 16 + (j ^ (l & 7))] = v;
        }
    }

    const float4* kg = (const float4*)k;
    for (int s0 = 0; s0 < S_; s0 += TILE_S_) {
        __syncthreads();
        for (int i = t; i < TILE_S_ * 16; i += 256) {
            int sr = i >> 4, j = i & 15;
            float4 v = kg[(size_t)((b * S_ + (s0 + sr)) * H_ + h) * 16 + j];
            ((float4*)k_t)[sr * 16 + (j ^ (sr & 7))] = v;
        }
        __syncthreads();

        int base = g_off[c * S_ + s0];
        int end  = g_off[c * S_ + s0 + TILE_S_];
        for (int e = base + t; e < end; e += 256) {
            int pk = g_pairs[e];
            int lr = pk & (CHUNK_ - 1);
            int sr = (pk >> 11) & (TILE_S_ - 1);
            const float4* qr = (const float4*)q_s + lr * 16;
            const float4* kr = (const float4*)k_t + sr * 16;
            float acc = 0.f;
            #pragma unroll
            for (int j = 0; j < 16; j++) {
                float4 a  = qr[j ^ (lr & 7)];
                float4 bb = kr[j ^ (sr & 7)];
                acc += a.x * bb.x + a.y * bb.y + a.z * bb.z + a.w * bb.w;
            }
            atomicMax(&m_max[lr], ford(acc));
            atomicAdd(&m_sum[lr], acc);
        }
    }
    __syncthreads();

    if (t < CHUNK_) {
        float mx = funord(m_max[t]);
        g_M[(size_t)(b * H_ + h) * L_ + c * CHUNK_ + t] =
            mx - m_sum[t] * (1.0f / (float)S_);
    }
}

// ---------------------------------------------------------------------------
// K2: top-40 per (b,h), register-resident iterative argmax on packed keys.
// ---------------------------------------------------------------------------
__global__ __launch_bounds__(1024) void k_topk() {
    int bh = blockIdx.x, t = threadIdx.x;
    int lane = t & 31, w = t >> 5;
    float v0 = g_M[(size_t)bh * L_ + 2 * t];
    float v1 = g_M[(size_t)bh * L_ + 2 * t + 1];

    __shared__ unsigned long long wbest[32];
    __shared__ unsigned long long winner;

    for (int it = 0; it < NTOP_; it++) {
        unsigned long long k0 =
            ((unsigned long long)ford(v0) << 32) | (unsigned)(~(2 * t));
        unsigned long long k1 =
            ((unsigned long long)ford(v1) << 32) | (unsigned)(~(2 * t + 1));
        unsigned long long kb = k0 > k1 ? k0 : k1;
        #pragma unroll
        for (int o = 16; o; o >>= 1) {
            unsigned long long ot = __shfl_xor_sync(0xFFFFFFFFu, kb, o);
            if (ot > kb) kb = ot;
        }
        if (lane == 0) wbest[w] = kb;
        __syncthreads();
        if (w == 0) {
            unsigned long long kk = wbest[lane];
            #pragma unroll
            for (int o = 16; o; o >>= 1) {
                unsigned long long ot = __shfl_xor_sync(0xFFFFFFFFu, kk, o);
                if (ot > kk) kk = ot;
            }
            if (lane == 0) winner = kk;
        }
        __syncthreads();
        unsigned widx = ~(unsigned)(winner & 0xFFFFFFFFu);
        if (t == 0) g_top[bh * NTOP_ + it] = (int)widx;
        if (widx == (unsigned)(2 * t))     v0 = -CUDART_INF_F;
        if (widx == (unsigned)(2 * t + 1)) v1 = -CUDART_INF_F;
    }
}

// ---------------------------------------------------------------------------
// K3: vmean — 256 blocks (bh x 8 s-splits), atomic accumulate into g_vmean.
// g_vmean pre-zeroed by k_zero.
// ---------------------------------------------------------------------------
__global__ void k_vmean(const float* __restrict__ v) {
    int bh = blockIdx.x >> 3, split = blockIdx.x & 7;
    int b = bh >> 3, h = bh & 7;
    int tid = threadIdx.x;
    int d = tid & 63, g = tid >> 6;
    int r0 = split * 256;
    float s = 0.f;
    #pragma unroll 4
    for (int r = r0 + g; r < r0 + 256; r += 4)
        s += v[(((size_t)(b * S_ + r)) * H_ + h) * D_ + d];
    __shared__ float part[4][D_];
    part[g][d] = s;
    __syncthreads();
    if (g == 0) {
        float tot = (part[0][d] + part[1][d] + part[2][d] + part[3][d]);
        atomicAdd(&g_vmean[bh * D_ + d], tot * (1.0f / (float)S_));
    }
}

// ---------------------------------------------------------------------------
// K4: out[b,l,h,d] = vmean[bh,d]
// ---------------------------------------------------------------------------
__global__ void k_fill(float4* __restrict__ out) {
    unsigned i = blockIdx.x * blockDim.x + threadIdx.x;
    if (i >= (unsigned)(B_ * L_ * H_ * (D_ / 4))) return;
    unsigned d4 = i & 15u;
    unsigned h  = (i >> 4) & 7u;
    unsigned b  = i >> 18;
    const float4* vm = (const float4*)g_vmean;
    out[i] = __ldg(vm + ((b * H_ + h) * (D_ / 4) + d4));
}

// ---------------------------------------------------------------------------
// K5: dense attention for selected queries. 4 queries/block.
// Scores phase stages K in smem tiles (coalesced, swizzled) — no scattered LDG.
// Dyn smem: ATILE_ x 64 floats = 64 KB.
// ---------------------------------------------------------------------------
#define SMEM_ATTN_ (ATILE_ * D_ * 4)

__global__ __launch_bounds__(256) void k_attn(const float* __restrict__ q,
                                              const float* __restrict__ k,
                                              const float* __restrict__ v,
                                              float* __restrict__ out) {
    extern __shared__ float k_t[];          // [ATILE_][16 float4] swizzled
    int bh = blockIdx.x / QBLKS_;
    int qb = blockIdx.x % QBLKS_;
    int b = bh >> 3, h = bh & 7;
    int tid = threadIdx.x;

    __shared__ float sq[QPB_][D_];
    __shared__ float sc[QPB_][S_];          // 32 KB
    __shared__ float sZ[QPB_];
    __shared__ int   sl[QPB_];
    __shared__ float pr[4][QPB_][D_];

    if (tid < QPB_ * D_) {
        int qi = tid >> 6, d = tid & 63;
        int lsel = g_top[bh * NTOP_ + qb * QPB_ + qi];
        if (d == 0) sl[qi] = lsel;
        sq[qi][d] = q[(((size_t)(b * L_ + lsel)) * H_ + h) * D_ + d] * SCALE_;
    }
    __syncthreads();

    // Scores: tile K through smem; thread tid owns row tid of each tile.
    const float4* kg = (const float4*)k;
    for (int s0 = 0; s0 < S_; s0 += ATILE_) {
        __syncthreads();
        for (int i = tid; i < ATILE_ * 16; i += 256) {
            int r = i >> 4, j = i & 15;
            ((float4*)k_t)[r * 16 + (j ^ (r & 15))] =
                kg[(size_t)((b * S_ + (s0 + r)) * H_ + h) * 16 + j];
        }
        __syncthreads();

        int r = tid;                         // 256 threads, 256 rows
        const float4* kr = (const float4*)k_t + r * 16;
        const float4* q0 = (const float4*)sq[0];
        const float4* q1 = (const float4*)sq[1];
        const float4* q2 = (const float4*)sq[2];
        const float4* q3 = (const float4*)sq[3];
        float a0 = 0.f, a1 = 0.f, a2 = 0.f, a3 = 0.f;
        #pragma unroll
        for (int j = 0; j < 16; j++) {
            float4 kv = kr[j ^ (r & 15)];
            float4 qa = q0[j];
            a0 += qa.x * kv.x + qa.y * kv.y + qa.z * kv.z + qa.w * kv.w;
            float4 qc = q1[j];
            a1 += qc.x * kv.x + qc.y * kv.y + qc.z * kv.z + qc.w * kv.w;
            float4 qd = q2[j];
            a2 += qd.x * kv.x + qd.y * kv.y + qd.z * kv.z + qd.w * kv.w;
            float4 qe = q3[j];
            a3 += qe.x * kv.x + qe.y * kv.y + qe.z * kv.z + qe.w * kv.w;
        }
        sc[0][s0 + r] = a0;
        sc[1][s0 + r] = a1;
        sc[2][s0 + r] = a2;
        sc[3][s0 + r] = a3;
    }
    __syncthreads();

    // Softmax: warp qi handles query qi
    int w = tid >> 5, lane = tid & 31;
    if (w < QPB_) {
        float mx = -CUDART_INF_F;
        for (int s = lane; s < S_; s += 32) mx = fmaxf(mx, sc[w][s]);
        #pragma unroll
        for (int o = 16; o; o >>= 1) mx = fmaxf(mx, __shfl_xor_sync(0xFFFFFFFFu, mx, o));
        float sum = 0.f;
        for (int s = lane; s < S_; s += 32) {
            float e = __expf(sc[w][s] - mx);
            sc[w][s] = e;
            sum += e;
        }
        #pragma unroll
        for (int o = 16; o; o >>= 1) sum += __shfl_xor_sync(0xFFFFFFFFu, sum, o);
        if (lane == 0) sZ[w] = sum;
    }
    __syncthreads();

    // AV: thread = (d, g); coalesced v reads.
    int d = tid & 63, g = tid >> 6;
    float acc[QPB_] = {0.f, 0.f, 0.f, 0.f};
    #pragma unroll 4
    for (int s = g; s < S_; s += 4) {
        float vv = v[(((size_t)(b * S_ + s)) * H_ + h) * D_ + d];
        #pragma unroll
        for (int qi = 0; qi < QPB_; qi++) acc[qi] += sc[qi][s] * vv;
    }
    #pragma unroll
    for (int qi = 0; qi < QPB_; qi++) pr[g][qi][d] = acc[qi];
    __syncthreads();
    if (g < QPB_) {
        int qi = g;
        float r = (pr[0][qi][d] + pr[1][qi][d] + pr[2][qi][d] + pr[3][qi][d]) / sZ[qi];
        out[(((size_t)(b * L_ + sl[qi])) * H_ + h) * D_ + d] = r;
    }
}

// ---------------------------------------------------------------------------
extern "C" void kernel_launch(void* const* d_in, const int* in_sizes, int n_in,
                              void* d_out, int out_size) {
    const float* q   = (const float*)d_in[0];
    const float* k   = (const float*)d_in[1];
    const float* v   = (const float*)d_in[2];
    const int*   idx = (const int*)d_in[3];
    float* out = (float*)d_out;

    cudaFuncSetAttribute(k_sample, cudaFuncAttributeMaxDynamicSharedMemorySize,
                         SMEM_SAMPLE_);
    cudaFuncSetAttribute(k_attn, cudaFuncAttributeMaxDynamicSharedMemorySize,
                         SMEM_ATTN_);

    // Inverse index + vmean zero
    k_zero<<<(NBUCK_ + 255) / 256, 256>>>();
    k_hist<<<(NPAIR_ + 255) / 256, 256>>>(idx);
    k_scan<<<1, 1024>>>();
    k_scatter<<<(NPAIR_ + 255) / 256, 256>>>(idx);

    // mean(V) + broadcast fill
    k_vmean<<<BH_ * 8, 256>>>(v);
    {
        unsigned n4 = B_ * L_ * H_ * (D_ / 4);
        k_fill<<<(n4 + 255) / 256, 256>>>((float4*)out);
    }

    // s-major sampled QK -> M
    k_sample<<<B_ * H_ * NCHUNK_, 256, SMEM_SAMPLE_>>>(q, k);
    // top-40 per (b,h)
    k_topk<<<BH_, 1024>>>();
    // dense attention for selected rows
    k_attn<<<BH_ * QBLKS_, 256, SMEM_ATTN_>>>(q, k, v, out);
}